// round 3
// baseline (speedup 1.0000x reference)
#include <cuda_runtime.h>
#include <cstdint>
#include <cstddef>

#define IMH 224
#define IMW 224
#define NB  32
#define NO  64
#define TAPS 25

// Scratch: per-pixel patch squared-norm. Static __device__ array (no allocations).
__device__ float g_x2[NB * IMH * IMW];

__device__ __forceinline__ unsigned long long fma2(unsigned long long a,
                                                   unsigned long long b,
                                                   unsigned long long c) {
    unsigned long long d;
    asm("fma.rn.f32x2 %0, %1, %2, %3;" : "=l"(d) : "l"(a), "l"(b), "l"(c));
    return d;
}
__device__ __forceinline__ float fsqrt_approx(float x) {
    float r; asm("sqrt.approx.f32 %0, %1;" : "=f"(r) : "f"(x)); return r;
}
__device__ __forceinline__ float lo32(unsigned long long v) {
    return __uint_as_float((unsigned)(v & 0xffffffffull));
}
__device__ __forceinline__ float hi32(unsigned long long v) {
    return __uint_as_float((unsigned)(v >> 32));
}

// ---------------------------------------------------------------------------
// Pass 1: g_x2[b,h,w] = sum over 5x5 window (pad 2, zeros) of x^2
// Block: 256 threads = 8 rows x 32 cols of pixels. Grid: (7, 28, 32).
// ---------------------------------------------------------------------------
__global__ __launch_bounds__(256) void x2_kernel(const float* __restrict__ x) {
    __shared__ float t[12][36];
    const int b = blockIdx.z, hh = blockIdx.y * 8, ww = blockIdx.x * 32;
    const int tid = threadIdx.x;
    const float* xb = x + (size_t)b * IMH * IMW;

    for (int idx = tid; idx < 12 * 36; idx += 256) {
        int r = idx / 36, c = idx % 36;
        int hr = hh - 2 + r, wc = ww - 2 + c;
        float v = (hr >= 0 && hr < IMH && wc >= 0 && wc < IMW) ? xb[hr * IMW + wc] : 0.f;
        t[r][c] = v;
    }
    __syncthreads();

    const int r0 = tid >> 5, lane = tid & 31;
    float s = 0.f;
#pragma unroll
    for (int i = 0; i < 5; i++) {
#pragma unroll
        for (int j = 0; j < 5; j++) {
            float v = t[r0 + i][lane + j];
            s = fmaf(v, v, s);
        }
    }
    g_x2[((size_t)b * IMH + hh + r0) * IMW + ww + lane] = s;
}

// ---------------------------------------------------------------------------
// Pass 2: packed-f32x2 direct conv + distance epilogue.
// Block: 256 threads = 8 warps. Each warp handles 4 output channels
// (o = og*32 + warp*4 + oo) over an 8-row x 32-col pixel tile.
// Each thread: 1 column (lane), 8 vertical pixels as 4 f32x2 pairs, 4 o's.
// Grid: (14, 28, 32) where blockIdx.x = ct*2 + og.
//
// SMEM input tile is stored COLUMN-major with stride 18 floats (72 B:
// 9*lane mod 16 is a permutation -> conflict-free LDS.64) in TWO copies:
// sA = rows as-is (even vertical pairs), sB = shifted by one row (odd pairs).
// Weights duplicated as {w,w} float2 so the packed multiplier is a single
// broadcast LDS.64 (no register packing MOVs).
// ---------------------------------------------------------------------------
__global__ __launch_bounds__(256, 2) void conv_dist_kernel(
    const float* __restrict__ x,
    const float* __restrict__ weight,
    float* __restrict__ out) {

    __shared__ float  sA[36 * 18];
    __shared__ float  sB[36 * 18];
    __shared__ float2 wdup[32 * TAPS];
    __shared__ float  w2s[32];

    const int ct = blockIdx.x >> 1, og = blockIdx.x & 1;
    const int rt = blockIdx.y, b = blockIdx.z;
    const int hh = rt * 8, ww = ct * 32;
    const int tid = threadIdx.x, lane = tid & 31, warp = tid >> 5;

    // Load input tile (rows hh-2..hh+9, cols ww-2..ww+33), zero-padded.
    const float* xb = x + (size_t)b * IMH * IMW;
    for (int idx = tid; idx < 12 * 36; idx += 256) {
        int r = idx / 36, c = idx % 36;
        int hr = hh - 2 + r, wc = ww - 2 + c;
        float v = (hr >= 0 && hr < IMH && wc >= 0 && wc < IMW) ? xb[hr * IMW + wc] : 0.f;
        sA[c * 18 + r] = v;
        if (r >= 1) sB[c * 18 + r - 1] = v;
    }
    // Duplicated weights for this block's 32 channels.
    for (int idx = tid; idx < 32 * TAPS; idx += 256) {
        int ol = idx / TAPS, t = idx % TAPS;
        float w = weight[(og * 32 + ol) * TAPS + t];
        wdup[idx] = make_float2(w, w);
    }
    // ||w||^2 per channel.
    if (tid < 32) {
        const float* wrow = weight + (og * 32 + tid) * TAPS;
        float s = 0.f;
#pragma unroll
        for (int t = 0; t < TAPS; t++) s = fmaf(wrow[t], wrow[t], s);
        w2s[tid] = s;
    }
    __syncthreads();

    const int ol0 = warp * 4;

    unsigned long long acc[4][4];
#pragma unroll
    for (int oo = 0; oo < 4; oo++)
#pragma unroll
        for (int q = 0; q < 4; q++) acc[oo][q] = 0ull;

#pragma unroll
    for (int j = 0; j < 5; j++) {
        const float* colA = sA + (lane + j) * 18;
        const float* colB = sB + (lane + j) * 18;
        unsigned long long ev[6], od[5];
#pragma unroll
        for (int k = 0; k < 6; k++) ev[k] = *(const unsigned long long*)(colA + 2 * k);
#pragma unroll
        for (int k = 0; k < 5; k++) od[k] = *(const unsigned long long*)(colB + 2 * k);

#pragma unroll
        for (int i = 0; i < 5; i++) {
#pragma unroll
            for (int oo = 0; oo < 4; oo++) {
                unsigned long long wv =
                    *(const unsigned long long*)&wdup[(ol0 + oo) * TAPS + i * 5 + j];
#pragma unroll
                for (int q = 0; q < 4; q++) {
                    // pixel pair q covers rows (2q+i, 2q+i+1) of the tile column
                    unsigned long long xp = ((i & 1) == 0) ? ev[q + (i >> 1)]
                                                           : od[q + ((i - 1) >> 1)];
                    acc[oo][q] = fma2(xp, wv, acc[oo][q]);
                }
            }
        }
    }

    // Epilogue: dist = sqrt(max(x2 + w2 - 2*xw, 0))
    float x2v[8];
    const float* x2p = g_x2 + ((size_t)b * IMH + hh) * IMW + ww + lane;
#pragma unroll
    for (int p = 0; p < 8; p++) x2v[p] = x2p[p * IMW];

#pragma unroll
    for (int oo = 0; oo < 4; oo++) {
        const int o = og * 32 + ol0 + oo;
        const float w2v = w2s[ol0 + oo];
        float* outp = out + (((size_t)b * NO + o) * IMH + hh) * IMW + ww + lane;
#pragma unroll
        for (int q = 0; q < 4; q++) {
            float xw0 = lo32(acc[oo][q]);
            float xw1 = hi32(acc[oo][q]);
            float d0 = fmaxf(fmaf(xw0, -2.f, x2v[2 * q] + w2v), 0.f);
            float d1 = fmaxf(fmaf(xw1, -2.f, x2v[2 * q + 1] + w2v), 0.f);
            outp[(2 * q) * IMW]     = fsqrt_approx(d0);
            outp[(2 * q + 1) * IMW] = fsqrt_approx(d1);
        }
    }
}

extern "C" void kernel_launch(void* const* d_in, const int* in_sizes, int n_in,
                              void* d_out, int out_size) {
    (void)in_sizes; (void)n_in; (void)out_size;
    const float* x = (const float*)d_in[0];
    const float* w = (const float*)d_in[1];
    float* out = (float*)d_out;

    x2_kernel<<<dim3(7, 28, 32), 256>>>(x);
    conv_dist_kernel<<<dim3(14, 28, 32), 256>>>(x, w, out);
}

// round 5
// speedup vs baseline: 1.6824x; 1.6824x over previous
#include <cuda_runtime.h>
#include <cstdint>
#include <cstddef>

#define IMH 224
#define IMW 224
#define NB  32
#define NO  64
#define PLANE (IMH * IMW)
#define NTILES (NB * 56 * 7)   // 4-row x 32-col pixel tiles
#define GRIDSZ (148 * 4)

#define SB_STRIDE 136          // floats per k-row of B (conflict-free: 136%32=8)

__device__ __forceinline__ float fsqrt_approx(float x) {
    float r; asm("sqrt.approx.f32 %0, %1;" : "=f"(r) : "f"(x)); return r;
}
__device__ __forceinline__ uint32_t f2tf32(float v) {
    uint32_t u; asm("cvt.rna.tf32.f32 %0, %1;" : "=r"(u) : "f"(v)); return u;
}
__device__ __forceinline__ void mma_tf32(float& c0, float& c1, float& c2, float& c3,
                                         uint32_t a0, uint32_t a1, uint32_t a2, uint32_t a3,
                                         uint32_t b0, uint32_t b1) {
    asm volatile(
        "mma.sync.aligned.m16n8k8.row.col.f32.tf32.tf32.f32 "
        "{%0,%1,%2,%3}, {%4,%5,%6,%7}, {%8,%9}, {%0,%1,%2,%3};"
        : "+f"(c0), "+f"(c1), "+f"(c2), "+f"(c3)
        : "r"(a0), "r"(a1), "r"(a2), "r"(a3), "r"(b0), "r"(b1));
}

// ---------------------------------------------------------------------------
// Persistent tf32 mma.sync kernel.
// CTA = 128 threads = 4 warps. Tile = 4 pixel rows x 32 cols; warp w owns
// pixel row (hh + w), its 32 lanes = 32 pixel columns.
// GEMM per warp: M = 64 channels (4 m16 tiles), N = 32 pixels (4 n8 tiles),
// K = 32 (25 taps zero-padded), via m16n8k8 tf32 mma.sync.
//   A (weights)  : prebuilt fragment table in SMEM, LDS.128 per (m,ks).
//   B (im2col)   : k-major SMEM [32 k][128 pix], built per tile with fp32 x2
//                  accumulated on the side.
// Epilogue: dist = sqrt(max(x2 + w2 - 2*xw, 0)), STG.64 of pixel pairs
// (fully coalesced 128B rows per channel).
// ---------------------------------------------------------------------------
__global__ __launch_bounds__(128, 4)
void conv_dist_mma(const float* __restrict__ x,
                   const float* __restrict__ wgt,
                   float* __restrict__ out) {
    __shared__ uint32_t sB[32 * SB_STRIDE];            // im2col, tf32 bits
    __shared__ __align__(16) uint32_t sWf[4 * 4 * 32 * 4]; // [ks][m][lane][slot]
    __shared__ float sX2[128];
    __shared__ float sW2[NO];

    const int tid  = threadIdx.x;
    const int wid  = tid >> 5;
    const int lane = tid & 31;
    const int g    = lane >> 2;     // groupID
    const int tig  = lane & 3;      // thread-in-group

    // ---- Stage weight fragments (once per CTA) ----
    // slot: a0=(g,c) a1=(g+8,c) a2=(g,c+4) a3=(g+8,c+4); row=m*16+..., col=ks*8+...
    for (int idx = tid; idx < 2048; idx += 128) {
        const int slot = idx & 3;
        const int ln   = (idx >> 2) & 31;
        const int m    = (idx >> 7) & 3;
        const int ks   = idx >> 9;
        const int row  = m * 16 + (ln >> 2) + ((slot & 1) ? 8 : 0);
        const int col  = ks * 8 + (ln & 3) + ((slot & 2) ? 4 : 0);
        const float v  = (col < 25) ? wgt[row * 25 + col] : 0.f;
        sWf[idx] = f2tf32(v);
    }
    if (tid < NO) {
        const float* wr = wgt + tid * 25;
        float s = 0.f;
#pragma unroll
        for (int t = 0; t < 25; t++) s = fmaf(wr[t], wr[t], s);
        sW2[tid] = s;
    }
    __syncthreads();

    for (int tI = blockIdx.x; tI < NTILES; tI += gridDim.x) {
        const int b  = tI / 392;
        const int r2 = tI % 392;
        const int hh = (r2 / 7) * 4;
        const int ww = (r2 % 7) * 32;
        const int ph = hh + wid;        // this thread's pixel row
        const int pw = ww + lane;       // this thread's pixel col

        // ---- im2col into sB (k-major) + fp32 x2 ----
        const float* xb = x + (size_t)b * PLANE;
        float x2 = 0.f;
#pragma unroll
        for (int k = 0; k < 32; k++) {
            float v = 0.f;
            if (k < 25) {
                const int i = k / 5, j = k % 5;
                const int h = ph + i - 2, w = pw + j - 2;
                if ((unsigned)h < IMH && (unsigned)w < IMW)
                    v = __ldg(xb + h * IMW + w);
            }
            x2 = fmaf(v, v, x2);
            sB[k * SB_STRIDE + tid] = f2tf32(v);
        }
        sX2[tid] = x2;
        __syncthreads();

        // ---- GEMM: C[4m][4nt][4] ----
        float c[4][4][4];
#pragma unroll
        for (int m = 0; m < 4; m++)
#pragma unroll
            for (int nt = 0; nt < 4; nt++)
#pragma unroll
                for (int q = 0; q < 4; q++) c[m][nt][q] = 0.f;

#pragma unroll
        for (int ks = 0; ks < 4; ks++) {
            // B fragments: b0 = B[ks*8+tig][pix nt*8+g], b1 = +4 k-rows
            uint32_t bf[4][2];
            const int bbase = (ks * 8 + tig) * SB_STRIDE + wid * 32 + g;
#pragma unroll
            for (int nt = 0; nt < 4; nt++) {
                bf[nt][0] = sB[bbase + nt * 8];
                bf[nt][1] = sB[bbase + 4 * SB_STRIDE + nt * 8];
            }
            // A fragments: one LDS.128 per m
#pragma unroll
            for (int m = 0; m < 4; m++) {
                const uint4 af = *(const uint4*)&sWf[((ks * 4 + m) * 32 + lane) * 4];
#pragma unroll
                for (int nt = 0; nt < 4; nt++)
                    mma_tf32(c[m][nt][0], c[m][nt][1], c[m][nt][2], c[m][nt][3],
                             af.x, af.y, af.z, af.w, bf[nt][0], bf[nt][1]);
            }
        }

        // ---- Epilogue ----
        float x2p[4][2];
#pragma unroll
        for (int nt = 0; nt < 4; nt++) {
            const float2 v = *(const float2*)&sX2[wid * 32 + nt * 8 + 2 * tig];
            x2p[nt][0] = v.x; x2p[nt][1] = v.y;
        }

        const size_t base = (size_t)b * NO * PLANE + (size_t)ph * IMW + ww;
#pragma unroll
        for (int m = 0; m < 4; m++) {
            const int ch0 = m * 16 + g;
            const float w20 = sW2[ch0];
            const float w21 = sW2[ch0 + 8];
            float* o0 = out + base + (size_t)ch0 * PLANE;
            float* o1 = o0 + (size_t)8 * PLANE;
#pragma unroll
            for (int nt = 0; nt < 4; nt++) {
                const int pc = nt * 8 + 2 * tig;
                float2 r0, r1;
                r0.x = fsqrt_approx(fmaxf(fmaf(c[m][nt][0], -2.f, x2p[nt][0] + w20), 0.f));
                r0.y = fsqrt_approx(fmaxf(fmaf(c[m][nt][1], -2.f, x2p[nt][1] + w20), 0.f));
                r1.x = fsqrt_approx(fmaxf(fmaf(c[m][nt][2], -2.f, x2p[nt][0] + w21), 0.f));
                r1.y = fsqrt_approx(fmaxf(fmaf(c[m][nt][3], -2.f, x2p[nt][1] + w21), 0.f));
                *(float2*)(o0 + pc) = r0;
                *(float2*)(o1 + pc) = r1;
            }
        }
        __syncthreads();   // protect sB/sX2 before next tile's stores
    }
}

extern "C" void kernel_launch(void* const* d_in, const int* in_sizes, int n_in,
                              void* d_out, int out_size) {
    (void)in_sizes; (void)n_in; (void)out_size;
    const float* x = (const float*)d_in[0];
    const float* w = (const float*)d_in[1];
    float* out = (float*)d_out;
    conv_dist_mma<<<GRIDSZ, 128>>>(x, w, out);
}

// round 6
// speedup vs baseline: 1.9299x; 1.1471x over previous
#include <cuda_runtime.h>
#include <cstdint>
#include <cstddef>

#define IMH 224
#define IMW 224
#define NB  32
#define NO  64
#define PLANE (IMH * IMW)
#define NTILES (NB * 56 * 7)   // 4-row x 32-col pixel tiles
#define GRIDSZ (148 * 4)

#define SB_STRIDE 136          // floats per k-row of B (conflict-free: 136%32=8)

__device__ __forceinline__ float fsqrt_approx(float x) {
    float r; asm("sqrt.approx.f32 %0, %1;" : "=f"(r) : "f"(x)); return r;
}
__device__ __forceinline__ uint32_t f2tf32(float v) {
    uint32_t u; asm("cvt.rna.tf32.f32 %0, %1;" : "=r"(u) : "f"(v)); return u;
}
__device__ __forceinline__ void mma_tf32(float& c0, float& c1, float& c2, float& c3,
                                         uint32_t a0, uint32_t a1, uint32_t a2, uint32_t a3,
                                         uint32_t b0, uint32_t b1) {
    asm volatile(
        "mma.sync.aligned.m16n8k8.row.col.f32.tf32.tf32.f32 "
        "{%0,%1,%2,%3}, {%4,%5,%6,%7}, {%8,%9}, {%0,%1,%2,%3};"
        : "+f"(c0), "+f"(c1), "+f"(c2), "+f"(c3)
        : "r"(a0), "r"(a1), "r"(a2), "r"(a3), "r"(b0), "r"(b1));
}

// Load the 25 taps of pixel (ph, pw) of image b into v[]. Interior fast path.
__device__ __forceinline__ void load_taps(float* v, const float* __restrict__ x,
                                          int b, int hh, int ww, int ph, int pw) {
    const float* xb = x + (size_t)b * PLANE;
    if (hh >= 2 && hh <= IMH - 6 && ww >= 2 && ww <= IMW - 34) {
        const float* p = xb + (ph - 2) * IMW + (pw - 2);
#pragma unroll
        for (int i = 0; i < 5; i++)
#pragma unroll
            for (int j = 0; j < 5; j++)
                v[i * 5 + j] = __ldg(p + i * IMW + j);
    } else {
#pragma unroll
        for (int i = 0; i < 5; i++)
#pragma unroll
            for (int j = 0; j < 5; j++) {
                const int h = ph + i - 2, w = pw + j - 2;
                float t = 0.f;
                if ((unsigned)h < IMH && (unsigned)w < IMW)
                    t = __ldg(xb + h * IMW + w);
                v[i * 5 + j] = t;
            }
    }
}

// ---------------------------------------------------------------------------
// Persistent tf32 mma.sync kernel, software-pipelined.
// CTA = 128 threads = 4 warps. Tile = 4 pixel rows x 32 cols; warp w owns
// pixel row (hh + w). Per warp GEMM: M=64 ch, N=32 px, K=32 (25 padded).
// Pipeline: prefetch next tile's 25 LDGs into regs before current GEMM;
// double-buffered sB/sX2 -> ONE syncthreads per tile.
// GEMM in 2 m-passes (2 m-tiles each); B fragments cached in regs across
// passes; pass-0 epilogue overlaps pass-1 mma.
// ---------------------------------------------------------------------------
__global__ __launch_bounds__(128, 4)
void conv_dist_mma(const float* __restrict__ x,
                   const float* __restrict__ wgt,
                   float* __restrict__ out) {
    __shared__ uint32_t sB[2][32 * SB_STRIDE];             // im2col tf32 bits
    __shared__ __align__(16) uint32_t sWf[4 * 4 * 32 * 4]; // [ks][m][lane][slot]
    __shared__ float sX2[2][128];
    __shared__ float sW2[NO];

    const int tid  = threadIdx.x;
    const int wid  = tid >> 5;
    const int lane = tid & 31;
    const int g    = lane >> 2;     // groupID
    const int tig  = lane & 3;      // thread-in-group

    // ---- one-time init: weight fragments, w2, zero sB (covers k=25..31) ----
    for (int idx = tid; idx < 2 * 32 * SB_STRIDE; idx += 128) {
        ((uint32_t*)sB)[idx] = 0u;
    }
    for (int idx = tid; idx < 2048; idx += 128) {
        const int slot = idx & 3;
        const int ln   = (idx >> 2) & 31;
        const int m    = (idx >> 7) & 3;
        const int ks   = idx >> 9;
        const int row  = m * 16 + (ln >> 2) + ((slot & 1) ? 8 : 0);
        const int col  = ks * 8 + (ln & 3) + ((slot & 2) ? 4 : 0);
        const float v  = (col < 25) ? wgt[row * 25 + col] : 0.f;
        sWf[idx] = f2tf32(v);
    }
    if (tid < NO) {
        const float* wr = wgt + tid * 25;
        float s = 0.f;
#pragma unroll
        for (int t = 0; t < 25; t++) s = fmaf(wr[t], wr[t], s);
        sW2[tid] = s;
    }
    __syncthreads();

    // ---- prologue: prefetch first tile ----
    int tI = blockIdx.x;
    float v[25];
    if (tI < NTILES) {
        const int b  = tI / 392, r2 = tI % 392;
        const int hh = (r2 / 7) * 4, ww = (r2 % 7) * 32;
        load_taps(v, x, b, hh, ww, hh + wid, ww + lane);
    }

    int buf = 0;
    for (; tI < NTILES; tI += gridDim.x, buf ^= 1) {
        const int b  = tI / 392, r2 = tI % 392;
        const int hh = (r2 / 7) * 4, ww = (r2 % 7) * 32;
        const int ph = hh + wid;

        // ---- store prefetched taps -> sB[buf], fp32 x2 ----
        float x2 = 0.f;
#pragma unroll
        for (int k = 0; k < 25; k++) {
            x2 = fmaf(v[k], v[k], x2);
            sB[buf][k * SB_STRIDE + tid] = f2tf32(v[k]);
        }
        sX2[buf][tid] = x2;
        __syncthreads();

        // ---- prefetch NEXT tile's taps (hidden behind GEMM below) ----
        const int nI = tI + gridDim.x;
        if (nI < NTILES) {
            const int nb  = nI / 392, nr2 = nI % 392;
            const int nhh = (nr2 / 7) * 4, nww = (nr2 % 7) * 32;
            load_taps(v, x, nb, nhh, nww, nhh + wid, nww + lane);
        }

        // ---- load ALL B fragments (cached across both m-passes) ----
        uint32_t bf[4][4][2];
#pragma unroll
        for (int ks = 0; ks < 4; ks++) {
            const int bbase = (ks * 8 + tig) * SB_STRIDE + wid * 32 + g;
#pragma unroll
            for (int nt = 0; nt < 4; nt++) {
                bf[ks][nt][0] = sB[buf][bbase + nt * 8];
                bf[ks][nt][1] = sB[buf][bbase + 4 * SB_STRIDE + nt * 8];
            }
        }

        // x2 pairs for epilogue (broadcast reads)
        float x2p[4][2];
#pragma unroll
        for (int nt = 0; nt < 4; nt++) {
            const float2 t2 = *(const float2*)&sX2[buf][wid * 32 + nt * 8 + 2 * tig];
            x2p[nt][0] = t2.x; x2p[nt][1] = t2.y;
        }

        const size_t base = (size_t)b * NO * PLANE + (size_t)ph * IMW + ww;

        // ---- GEMM + epilogue in 2 m-passes ----
#pragma unroll
        for (int pass = 0; pass < 2; pass++) {
            float c[2][4][4];
#pragma unroll
            for (int mm = 0; mm < 2; mm++)
#pragma unroll
                for (int nt = 0; nt < 4; nt++)
#pragma unroll
                    for (int q = 0; q < 4; q++) c[mm][nt][q] = 0.f;

#pragma unroll
            for (int ks = 0; ks < 4; ks++) {
#pragma unroll
                for (int mm = 0; mm < 2; mm++) {
                    const int m = pass * 2 + mm;
                    const uint4 af = *(const uint4*)&sWf[((ks * 4 + m) * 32 + lane) * 4];
#pragma unroll
                    for (int nt = 0; nt < 4; nt++)
                        mma_tf32(c[mm][nt][0], c[mm][nt][1], c[mm][nt][2], c[mm][nt][3],
                                 af.x, af.y, af.z, af.w,
                                 bf[ks][nt][0], bf[ks][nt][1]);
                }
            }

            // epilogue for channels of this pass
#pragma unroll
            for (int mm = 0; mm < 2; mm++) {
                const int m = pass * 2 + mm;
                const int ch0 = m * 16 + g;
                const float w20 = sW2[ch0];
                const float w21 = sW2[ch0 + 8];
                float* o0 = out + base + (size_t)ch0 * PLANE;
                float* o1 = o0 + (size_t)8 * PLANE;
#pragma unroll
                for (int nt = 0; nt < 4; nt++) {
                    const int pc = nt * 8 + 2 * tig;
                    float2 r0, r1;
                    r0.x = fsqrt_approx(fmaxf(fmaf(c[mm][nt][0], -2.f, x2p[nt][0] + w20), 0.f));
                    r0.y = fsqrt_approx(fmaxf(fmaf(c[mm][nt][1], -2.f, x2p[nt][1] + w20), 0.f));
                    r1.x = fsqrt_approx(fmaxf(fmaf(c[mm][nt][2], -2.f, x2p[nt][0] + w21), 0.f));
                    r1.y = fsqrt_approx(fmaxf(fmaf(c[mm][nt][3], -2.f, x2p[nt][1] + w21), 0.f));
                    *(float2*)(o0 + pc) = r0;
                    *(float2*)(o1 + pc) = r1;
                }
            }
        }
    }
}

extern "C" void kernel_launch(void* const* d_in, const int* in_sizes, int n_in,
                              void* d_out, int out_size) {
    (void)in_sizes; (void)n_in; (void)out_size;
    const float* x = (const float*)d_in[0];
    const float* w = (const float*)d_in[1];
    float* out = (float*)d_out;
    conv_dist_mma<<<GRIDSZ, 128>>>(x, w, out);
}

// round 7
// speedup vs baseline: 2.1007x; 1.0885x over previous
#include <cuda_runtime.h>
#include <cstdint>
#include <cstddef>

#define IMH 224
#define IMW 224
#define NB  32
#define NO  64
#define PLANE (IMH * IMW)
#define TPI   196                 // tiles per image: 28 row-tiles x 7 col-tiles
#define NTILES (NB * TPI)         // 6272 tiles of 8 rows x 32 cols
#define GRIDSZ (148 * 4)
#define PADT  44                  // raw-tile row pitch (44 % 32 = 12 -> conflict-free)
#define TELEM (12 * 36)           // halo tile elements

__device__ __forceinline__ float fsqrt_approx(float x) {
    float r; asm("sqrt.approx.f32 %0, %1;" : "=f"(r) : "f"(x)); return r;
}
__device__ __forceinline__ float f2tf32f(float v) {
    float u; asm("cvt.rna.tf32.f32 %0, %1;" : "=f"(u) : "f"(v)); return u;
}
__device__ __forceinline__ void mma_tf32(float& c0, float& c1, float& c2, float& c3,
                                         uint32_t a0, uint32_t a1, uint32_t a2, uint32_t a3,
                                         float b0f, float b1f) {
    asm volatile(
        "mma.sync.aligned.m16n8k8.row.col.f32.tf32.tf32.f32 "
        "{%0,%1,%2,%3}, {%4,%5,%6,%7}, {%8,%9}, {%0,%1,%2,%3};"
        : "+f"(c0), "+f"(c1), "+f"(c2), "+f"(c3)
        : "r"(a0), "r"(a1), "r"(a2), "r"(a3),
          "r"(__float_as_uint(b0f)), "r"(__float_as_uint(b1f)));
}

// ---------------------------------------------------------------------------
// Persistent tf32 mma.sync kernel, raw-tile edition.
// CTA = 128 threads = 4 warps. Tile = 8 pixel rows x 32 cols; warp w owns
// pixel rows {hh+w, hh+w+4} (rt=0,1). GEMM per warp: M=64 ch, N=64 px, K=32.
// B fragments read straight from the raw 12x36 halo tile in SMEM (no im2col);
// x2 computed from the fragments via 2x shfl.bfly; A-fragment loads amortized
// over both row-tiles. One __syncthreads per iteration, double-buffered tile,
// register-prefetched next tile.
// ---------------------------------------------------------------------------
__global__ __launch_bounds__(128, 4)
void conv_dist_mma(const float* __restrict__ x,
                   const float* __restrict__ wgt,
                   float* __restrict__ out) {
    __shared__ float sT[2][12 * PADT];                     // raw halo tiles
    __shared__ __align__(16) uint32_t sWf[16 * 32 * 4];    // [m][ks][lane][slot]
    __shared__ __align__(8) float sX2[4][2][32];           // [warp][rt][pixel col]
    __shared__ float sW2[NO];

    const int tid  = threadIdx.x;
    const int wid  = tid >> 5;
    const int lane = tid & 31;
    const int g    = lane >> 2;
    const int tig  = lane & 3;

    // ---- one-time init: weight fragments + w2 ----
    for (int idx = tid; idx < 2048; idx += 128) {
        const int slot = idx & 3;
        const int ln   = (idx >> 2) & 31;
        const int ks   = (idx >> 7) & 3;
        const int m    = idx >> 9;
        const int row  = m * 16 + (ln >> 2) + ((slot & 1) ? 8 : 0);
        const int col  = ks * 8 + (ln & 3) + ((slot & 2) ? 4 : 0);
        const float v  = (col < 25) ? wgt[row * 25 + col] : 0.f;
        sWf[idx] = __float_as_uint(f2tf32f(v));
    }
    if (tid < NO) {
        const float* wr = wgt + tid * 25;
        float s = 0.f;
#pragma unroll
        for (int t = 0; t < 25; t++) s = fmaf(wr[t], wr[t], s);
        sW2[tid] = s;
    }

    // per-thread tap offsets within raw tile: q=0..6, k=4q+tig (clamped to 24)
    uint32_t off[7];
#pragma unroll
    for (int q = 0; q < 7; q++) {
        int k = 4 * q + tig; if (k > 24) k = 24;
        off[q] = (uint32_t)((k / 5) * PADT + (k % 5));
    }
    // SMEM store offsets for halo tile load (idx fixed per thread)
    uint32_t soff[4];
#pragma unroll
    for (int r = 0; r < 4; r++) {
        const int idx = tid + 128 * r;
        soff[r] = (idx < TELEM) ? (uint32_t)((idx / 36) * PADT + (idx % 36)) : 0u;
    }
    __syncthreads();

    // ---- prologue: prefetch first halo tile into regs ----
    int tI = blockIdx.x;
    float pv[4];
    {
        const int b = tI / TPI, r2 = tI % TPI;
        const int hh = (r2 / 7) * 8, ww = (r2 % 7) * 32;
        const float* xb = x + (size_t)b * PLANE;
#pragma unroll
        for (int r = 0; r < 4; r++) {
            const int idx = tid + 128 * r;
            float v = 0.f;
            if (idx < TELEM) {
                const int trow = idx / 36, tcol = idx % 36;
                const int h = hh - 2 + trow, w = ww - 2 + tcol;
                if ((unsigned)h < IMH && (unsigned)w < IMW)
                    v = __ldg(xb + h * IMW + w);
            }
            pv[r] = v;
        }
    }

    int buf = 0;
    for (; tI < NTILES; tI += gridDim.x, buf ^= 1) {
        const int b = tI / TPI, r2 = tI % TPI;
        const int hh = (r2 / 7) * 8, ww = (r2 % 7) * 32;

        // ---- store prefetched tile ----
#pragma unroll
        for (int r = 0; r < 4; r++)
            if (tid + 128 * r < TELEM) sT[buf][soff[r]] = pv[r];
        __syncthreads();

        // ---- prefetch NEXT tile (hidden behind GEMM) ----
        const int nI = tI + gridDim.x;
        if (nI < NTILES) {
            const int nb = nI / TPI, nr2 = nI % TPI;
            const int nhh = (nr2 / 7) * 8, nww = (nr2 % 7) * 32;
            const float* xb = x + (size_t)nb * PLANE;
#pragma unroll
            for (int r = 0; r < 4; r++) {
                const int idx = tid + 128 * r;
                float v = 0.f;
                if (idx < TELEM) {
                    const int trow = idx / 36, tcol = idx % 36;
                    const int h = nhh - 2 + trow, w = nww - 2 + tcol;
                    if ((unsigned)h < IMH && (unsigned)w < IMW)
                        v = __ldg(xb + h * IMW + w);
                }
                pv[r] = v;
            }
        }

        // ---- load B fragments straight from raw tile (+ tf32 round) ----
        float bfv[4][2][4][2];   // [ks][rt][nt][b]
        const float* tb0 = &sT[buf][(wid) * PADT + g];
        const float* tb1 = &sT[buf][(wid + 4) * PADT + g];
#pragma unroll
        for (int ks = 0; ks < 4; ks++) {
#pragma unroll
            for (int rt = 0; rt < 2; rt++) {
                const float* tb = rt ? tb1 : tb0;
#pragma unroll
                for (int nt = 0; nt < 4; nt++) {
                    float b0, b1;
                    if (ks < 3) {
                        b0 = tb[off[2 * ks] + nt * 8];
                        b1 = tb[off[2 * ks + 1] + nt * 8];
                    } else {
                        b0 = (tig == 0) ? tb[off[6] + nt * 8] : 0.f;
                        b1 = 0.f;
                    }
                    bfv[ks][rt][nt][0] = f2tf32f(b0);
                    bfv[ks][rt][nt][1] = f2tf32f(b1);
                }
            }
        }

        // ---- x2 from fragments: per (rt,nt) sum squares, reduce over tig ----
#pragma unroll
        for (int rt = 0; rt < 2; rt++) {
#pragma unroll
            for (int nt = 0; nt < 4; nt++) {
                float s = 0.f;
#pragma unroll
                for (int ks = 0; ks < 4; ks++) {
                    s = fmaf(bfv[ks][rt][nt][0], bfv[ks][rt][nt][0], s);
                    s = fmaf(bfv[ks][rt][nt][1], bfv[ks][rt][nt][1], s);
                }
                s += __shfl_xor_sync(0xffffffffu, s, 1);
                s += __shfl_xor_sync(0xffffffffu, s, 2);
                if (tig == 0) sX2[wid][rt][nt * 8 + g] = s;
            }
        }
        __syncwarp();

        const size_t obase = (size_t)b * NO * PLANE + (size_t)(hh + wid) * IMW + ww;

        // ---- GEMM + epilogue: 4 m-passes x 2 nt-halves ----
#pragma unroll
        for (int m = 0; m < 4; m++) {
            uint4 af[4];
#pragma unroll
            for (int ks = 0; ks < 4; ks++)
                af[ks] = *(const uint4*)&sWf[((m * 4 + ks) * 32 + lane) * 4];

            const int ch0 = m * 16 + g;
            const float w20 = sW2[ch0];
            const float w21 = sW2[ch0 + 8];
            float* o0 = out + obase + (size_t)ch0 * PLANE;
            float* o1 = o0 + (size_t)8 * PLANE;

#pragma unroll
            for (int nh = 0; nh < 2; nh++) {
                float c[2][2][4];
#pragma unroll
                for (int rt = 0; rt < 2; rt++)
#pragma unroll
                    for (int n2 = 0; n2 < 2; n2++)
#pragma unroll
                        for (int q = 0; q < 4; q++) c[rt][n2][q] = 0.f;

#pragma unroll
                for (int ks = 0; ks < 4; ks++)
#pragma unroll
                    for (int rt = 0; rt < 2; rt++)
#pragma unroll
                        for (int n2 = 0; n2 < 2; n2++)
                            mma_tf32(c[rt][n2][0], c[rt][n2][1],
                                     c[rt][n2][2], c[rt][n2][3],
                                     af[ks].x, af[ks].y, af[ks].z, af[ks].w,
                                     bfv[ks][rt][nh * 2 + n2][0],
                                     bfv[ks][rt][nh * 2 + n2][1]);

#pragma unroll
                for (int rt = 0; rt < 2; rt++) {
#pragma unroll
                    for (int n2 = 0; n2 < 2; n2++) {
                        const int nt = nh * 2 + n2;
                        const float2 xp = *(const float2*)&sX2[wid][rt][nt * 8 + 2 * tig];
                        const int pc = nt * 8 + 2 * tig + rt * 4 * IMW;
                        float2 r0v, r1v;
                        r0v.x = fsqrt_approx(fmaxf(fmaf(c[rt][n2][0], -2.f, xp.x + w20), 0.f));
                        r0v.y = fsqrt_approx(fmaxf(fmaf(c[rt][n2][1], -2.f, xp.y + w20), 0.f));
                        r1v.x = fsqrt_approx(fmaxf(fmaf(c[rt][n2][2], -2.f, xp.x + w21), 0.f));
                        r1v.y = fsqrt_approx(fmaxf(fmaf(c[rt][n2][3], -2.f, xp.y + w21), 0.f));
                        *(float2*)(o0 + pc) = r0v;
                        *(float2*)(o1 + pc) = r1v;
                    }
                }
            }
        }
    }
}

extern "C" void kernel_launch(void* const* d_in, const int* in_sizes, int n_in,
                              void* d_out, int out_size) {
    (void)in_sizes; (void)n_in; (void)out_size;
    const float* x = (const float*)d_in[0];
    const float* w = (const float*)d_in[1];
    float* out = (float*)d_out;
    conv_dist_mma<<<GRIDSZ, 128>>>(x, w, out);
}

// round 9
// speedup vs baseline: 2.2545x; 1.0732x over previous
#include <cuda_runtime.h>
#include <cstdint>
#include <cstddef>

#define IMH 224
#define IMW 224
#define NB  32
#define NO  64
#define PLANE (IMH * IMW)
#define TPI   196                 // tiles per image: 28 row-tiles x 7 col-tiles
#define NTILES (NB * TPI)         // 6272 tiles of 8 rows x 32 cols
#define GRIDSZ (148 * 5)
#define PADT  44                  // raw-tile row pitch (44 % 32 = 12 -> conflict-free)
#define TELEM (12 * 36)           // halo tile elements

__device__ __forceinline__ float fsqrt_approx(float x) {
    float r; asm("sqrt.approx.f32 %0, %1;" : "=f"(r) : "f"(x)); return r;
}
__device__ __forceinline__ float f2tf32f(float v) {
    float u; asm("cvt.rna.tf32.f32 %0, %1;" : "=f"(u) : "f"(v)); return u;
}
__device__ __forceinline__ void mma_tf32(float& c0, float& c1, float& c2, float& c3,
                                         uint32_t a0, uint32_t a1, uint32_t a2, uint32_t a3,
                                         float b0f, float b1f) {
    asm volatile(
        "mma.sync.aligned.m16n8k8.row.col.f32.tf32.tf32.f32 "
        "{%0,%1,%2,%3}, {%4,%5,%6,%7}, {%8,%9}, {%0,%1,%2,%3};"
        : "+f"(c0), "+f"(c1), "+f"(c2), "+f"(c3)
        : "r"(a0), "r"(a1), "r"(a2), "r"(a3),
          "r"(__float_as_uint(b0f)), "r"(__float_as_uint(b1f)));
}

// ---------------------------------------------------------------------------
// Persistent tf32 mma.sync kernel, raw-tile edition, 5 CTAs/SM.
// CTA = 128 threads = 4 warps. Tile = 8 pixel rows x 32 cols; warp w owns
// pixel rows {hh+w, hh+w+4} (rt=0,1). GEMM per warp: M=64 ch, N=64 px, K=32.
// nh (pixel-column half) is the OUTER loop so only half the B fragments are
// register-resident (32 regs) -> fits the 102-reg cap for 5 CTAs/SM.
// dist epilogue uses sqrt(|d2|) (free SASS abs modifier) instead of max(d2,0).
// ---------------------------------------------------------------------------
__global__ __launch_bounds__(128, 5)
void conv_dist_mma(const float* __restrict__ x,
                   const float* __restrict__ wgt,
                   float* __restrict__ out) {
    __shared__ float sT[2][12 * PADT];                     // raw halo tiles
    __shared__ __align__(16) uint32_t sWf[16 * 32 * 4];    // [m][ks][lane][slot]
    __shared__ __align__(8) float sX2[4][2][32];           // [warp][rt][pixel col]
    __shared__ float sW2[NO];

    const int tid  = threadIdx.x;
    const int wid  = tid >> 5;
    const int lane = tid & 31;
    const int g    = lane >> 2;
    const int tig  = lane & 3;

    // ---- one-time init: weight fragments + w2 ----
    for (int idx = tid; idx < 2048; idx += 128) {
        const int slot = idx & 3;
        const int ln   = (idx >> 2) & 31;
        const int ks   = (idx >> 7) & 3;
        const int m    = idx >> 9;
        const int row  = m * 16 + (ln >> 2) + ((slot & 1) ? 8 : 0);
        const int col  = ks * 8 + (ln & 3) + ((slot & 2) ? 4 : 0);
        const float v  = (col < 25) ? wgt[row * 25 + col] : 0.f;
        sWf[idx] = __float_as_uint(f2tf32f(v));
    }
    if (tid < NO) {
        const float* wr = wgt + tid * 25;
        float s = 0.f;
#pragma unroll
        for (int t = 0; t < 25; t++) s = fmaf(wr[t], wr[t], s);
        sW2[tid] = s;
    }

    // per-thread tap offsets within raw tile: q=0..6, k=4q+tig (clamped to 24)
    uint32_t off[7];
#pragma unroll
    for (int q = 0; q < 7; q++) {
        int k = 4 * q + tig; if (k > 24) k = 24;
        off[q] = (uint32_t)((k / 5) * PADT + (k % 5));
    }
    // SMEM store offsets for halo tile load (idx fixed per thread)
    uint32_t soff[4];
#pragma unroll
    for (int r = 0; r < 4; r++) {
        const int idx = tid + 128 * r;
        soff[r] = (idx < TELEM) ? (uint32_t)((idx / 36) * PADT + (idx % 36)) : 0u;
    }
    __syncthreads();

    // ---- prologue: prefetch first halo tile into regs ----
    int tI = blockIdx.x;
    float pv[4];
    {
        const int b = tI / TPI, r2 = tI % TPI;
        const int hh = (r2 / 7) * 8, ww = (r2 % 7) * 32;
        const float* xb = x + (size_t)b * PLANE;
#pragma unroll
        for (int r = 0; r < 4; r++) {
            const int idx = tid + 128 * r;
            float v = 0.f;
            if (idx < TELEM) {
                const int trow = idx / 36, tcol = idx % 36;
                const int h = hh - 2 + trow, w = ww - 2 + tcol;
                if ((unsigned)h < IMH && (unsigned)w < IMW)
                    v = __ldg(xb + h * IMW + w);
            }
            pv[r] = v;
        }
    }

    int buf = 0;
    for (; tI < NTILES; tI += gridDim.x, buf ^= 1) {
        const int b = tI / TPI, r2 = tI % TPI;
        const int hh = (r2 / 7) * 8, ww = (r2 % 7) * 32;

        // ---- store prefetched tile ----
#pragma unroll
        for (int r = 0; r < 4; r++)
            if (tid + 128 * r < TELEM) sT[buf][soff[r]] = pv[r];
        __syncthreads();

        // ---- prefetch NEXT tile (hidden behind GEMM) ----
        const int nI = tI + gridDim.x;
        if (nI < NTILES) {
            const int nb = nI / TPI, nr2 = nI % TPI;
            const int nhh = (nr2 / 7) * 8, nww = (nr2 % 7) * 32;
            const float* xb = x + (size_t)nb * PLANE;
#pragma unroll
            for (int r = 0; r < 4; r++) {
                const int idx = tid + 128 * r;
                float v = 0.f;
                if (idx < TELEM) {
                    const int trow = idx / 36, tcol = idx % 36;
                    const int h = nhh - 2 + trow, w = nww - 2 + tcol;
                    if ((unsigned)h < IMH && (unsigned)w < IMW)
                        v = __ldg(xb + h * IMW + w);
                }
                pv[r] = v;
            }
        }

        const size_t obase = (size_t)b * NO * PLANE + (size_t)(hh + wid) * IMW + ww;
        const float* tb0 = &sT[buf][(wid) * PADT + g];
        const float* tb1 = &sT[buf][(wid + 4) * PADT + g];

        // ---- process pixel-column halves: nt = 2*nh + nt2 ----
#pragma unroll
        for (int nh = 0; nh < 2; nh++) {
            // B fragments for this half (32 regs)
            float bfv[4][2][2][2];   // [ks][rt][nt2][b]
#pragma unroll
            for (int ks = 0; ks < 4; ks++) {
#pragma unroll
                for (int rt = 0; rt < 2; rt++) {
                    const float* tb = rt ? tb1 : tb0;
#pragma unroll
                    for (int nt2 = 0; nt2 < 2; nt2++) {
                        const int nt = 2 * nh + nt2;
                        float b0, b1;
                        if (ks < 3) {
                            b0 = tb[off[2 * ks] + nt * 8];
                            b1 = tb[off[2 * ks + 1] + nt * 8];
                        } else {
                            b0 = (tig == 0) ? tb[off[6] + nt * 8] : 0.f;
                            b1 = 0.f;
                        }
                        bfv[ks][rt][nt2][0] = f2tf32f(b0);
                        bfv[ks][rt][nt2][1] = f2tf32f(b1);
                    }
                }
            }

            // x2 for these pixels from the fragments
#pragma unroll
            for (int rt = 0; rt < 2; rt++) {
#pragma unroll
                for (int nt2 = 0; nt2 < 2; nt2++) {
                    float s = 0.f;
#pragma unroll
                    for (int ks = 0; ks < 4; ks++) {
                        s = fmaf(bfv[ks][rt][nt2][0], bfv[ks][rt][nt2][0], s);
                        s = fmaf(bfv[ks][rt][nt2][1], bfv[ks][rt][nt2][1], s);
                    }
                    s += __shfl_xor_sync(0xffffffffu, s, 1);
                    s += __shfl_xor_sync(0xffffffffu, s, 2);
                    if (tig == 0) sX2[wid][rt][(2 * nh + nt2) * 8 + g] = s;
                }
            }
            __syncwarp();

            float2 xp[2][2];
#pragma unroll
            for (int rt = 0; rt < 2; rt++)
#pragma unroll
                for (int nt2 = 0; nt2 < 2; nt2++)
                    xp[rt][nt2] = *(const float2*)
                        &sX2[wid][rt][(2 * nh + nt2) * 8 + 2 * tig];

            // ---- 4 m-passes over channels ----
#pragma unroll
            for (int m = 0; m < 4; m++) {
                uint4 af[4];
#pragma unroll
                for (int ks = 0; ks < 4; ks++)
                    af[ks] = *(const uint4*)&sWf[((m * 4 + ks) * 32 + lane) * 4];

                float c[2][2][4];
#pragma unroll
                for (int rt = 0; rt < 2; rt++)
#pragma unroll
                    for (int nt2 = 0; nt2 < 2; nt2++)
#pragma unroll
                        for (int q = 0; q < 4; q++) c[rt][nt2][q] = 0.f;

#pragma unroll
                for (int ks = 0; ks < 4; ks++)
#pragma unroll
                    for (int rt = 0; rt < 2; rt++)
#pragma unroll
                        for (int nt2 = 0; nt2 < 2; nt2++)
                            mma_tf32(c[rt][nt2][0], c[rt][nt2][1],
                                     c[rt][nt2][2], c[rt][nt2][3],
                                     af[ks].x, af[ks].y, af[ks].z, af[ks].w,
                                     bfv[ks][rt][nt2][0], bfv[ks][rt][nt2][1]);

                const int ch0 = m * 16 + g;
                const float w20 = sW2[ch0];
                const float w21 = sW2[ch0 + 8];
                float* o0 = out + obase + (size_t)ch0 * PLANE;
                float* o1 = o0 + (size_t)8 * PLANE;

#pragma unroll
                for (int rt = 0; rt < 2; rt++) {
#pragma unroll
                    for (int nt2 = 0; nt2 < 2; nt2++) {
                        const int nt = 2 * nh + nt2;
                        const float2 p = xp[rt][nt2];
                        const int pc = nt * 8 + 2 * tig + rt * 4 * IMW;
                        float2 r0v, r1v;
                        r0v.x = fsqrt_approx(fabsf(fmaf(c[rt][nt2][0], -2.f, p.x + w20)));
                        r0v.y = fsqrt_approx(fabsf(fmaf(c[rt][nt2][1], -2.f, p.y + w20)));
                        r1v.x = fsqrt_approx(fabsf(fmaf(c[rt][nt2][2], -2.f, p.x + w21)));
                        r1v.y = fsqrt_approx(fabsf(fmaf(c[rt][nt2][3], -2.f, p.y + w21)));
                        *(float2*)(o0 + pc) = r0v;
                        *(float2*)(o1 + pc) = r1v;
                    }
                }
            }
        }
    }
}

extern "C" void kernel_launch(void* const* d_in, const int* in_sizes, int n_in,
                              void* d_out, int out_size) {
    (void)in_sizes; (void)n_in; (void)out_size;
    const float* x = (const float*)d_in[0];
    const float* w = (const float*)d_in[1];
    float* out = (float*)d_out;
    conv_dist_mma<<<GRIDSZ, 128>>>(x, w, out);
}